// round 2
// baseline (speedup 1.0000x reference)
#include <cuda_runtime.h>

// HolographicFMLayer: batched all-pairs circular convolution.
// inputs: float32 [B, 24, 64]  ->  out: float32 [B, 276, 64]
// out[b,p,n] = sum_k x[b,i_p,k] * x[b,j_p,(n-k) mod 64], pairs = triu_indices(24, k=1)

#define NF      24
#define NPAIR   276
#define LEN     64
#define STRIDE  129            // 129 mod 32 == 1 -> distinct bank per field row
#define THREADS 576
#define PAIRS_PER_BLOCK 138    // 276 / 2 (gridDim.y = 2)
#define TASKS   (PAIRS_PER_BLOCK * 4)  // 4 windows of 16 n-values per pair

__global__ __launch_bounds__(THREADS, 2)
void holo_circconv_kernel(const float* __restrict__ in, float* __restrict__ out)
{
    // dup[f][m] = x[f][m % 64], m in [0,128); duplicated so (n-k) mod 64 becomes
    // a plain sliding index n - k + 64 in [1, 127].
    __shared__ float dup[NF * STRIDE];

    const int batch = blockIdx.x;
    const int pbase = blockIdx.y * PAIRS_PER_BLOCK;

    // ---- stage the batch's 24x64 tile into smem (duplicated along m) ----
    const float* __restrict__ src = in + (size_t)batch * (NF * LEN);
    for (int idx = threadIdx.x; idx < NF * LEN; idx += THREADS) {
        float v = src[idx];
        int f = idx >> 6;
        int c = idx & 63;
        dup[f * STRIDE + c]      = v;
        dup[f * STRIDE + c + 64] = v;
    }
    __syncthreads();

    const int t = threadIdx.x;
    if (t >= TASKS) return;

    // win-major task order: a warp spans ~32 consecutive pairs at one window
    // -> b-row loads hit 32 distinct banks (stride 129), a-loads likewise.
    const int win     = t / PAIRS_PER_BLOCK;
    const int p_local = t - win * PAIRS_PER_BLOCK;
    const int p       = pbase + p_local;
    const int n0      = win * 16;

    // decode (i, j) from pair index p (row-major triu, k=1)
    int i = 0, rem = p;
    while (rem >= NF - 1 - i) { rem -= NF - 1 - i; ++i; }
    const int j = i + 1 + rem;

    const float* __restrict__ ai = dup + i * STRIDE;
    const float* __restrict__ bj = dup + j * STRIDE;

    // Sliding window: before iteration k, w[q] == bj[n0 + q - k + 64].
    float w[16], acc[16];
#pragma unroll
    for (int q = 0; q < 16; ++q) {
        w[q]   = bj[n0 + 64 + q];
        acc[q] = 0.0f;
    }

#pragma unroll
    for (int k = 0; k < 64; ++k) {
        const float a = ai[k];             // broadcast within warp (same addr per pair)
#pragma unroll
        for (int q = 0; q < 16; ++q)
            acc[q] = fmaf(a, w[q], acc[q]);
        // slide window down by one (pure register renaming after full unroll)
        const float nw = bj[n0 + 63 - k];  // k==63 load is in-bounds, value unused
#pragma unroll
        for (int q = 15; q > 0; --q) w[q] = w[q - 1];
        w[0] = nw;
    }

    // ---- store 16 consecutive outputs as 4x float4 (64B aligned: n0 % 16 == 0) ----
    float4* __restrict__ dst =
        (float4*)(out + ((size_t)batch * NPAIR + p) * LEN + n0);
#pragma unroll
    for (int q = 0; q < 4; ++q)
        dst[q] = make_float4(acc[4*q + 0], acc[4*q + 1], acc[4*q + 2], acc[4*q + 3]);
}

extern "C" void kernel_launch(void* const* d_in, const int* in_sizes, int n_in,
                              void* d_out, int out_size)
{
    const float* in  = (const float*)d_in[0];
    float*       out = (float*)d_out;
    const int batches = in_sizes[0] / (NF * LEN);   // 2048 for the bench shape

    dim3 grid(batches, 2);
    holo_circconv_kernel<<<grid, THREADS>>>(in, out);
}

// round 3
// speedup vs baseline: 1.6102x; 1.6102x over previous
#include <cuda_runtime.h>
#include <cstdint>

// HolographicFMLayer: batched all-pairs circular convolution.
// inputs: float32 [B, 24, 64]  ->  out: float32 [B, 276, 64]
// out[b,p,n] = sum_k x[b,i,k] * x[b,j,(n-k) mod 64], pairs = triu_indices(24, k=1)
//
// Two-level CRT split: x^64-1 = (x^16-1)(x^16+1)(x^32+1)
//   per field f:  u = x_lo + x_hi (len 32), v = (x_lo - x_hi)/sqrt(2)   [mod x^32 -+ 1]
//                 P = (u_lo + u_hi)/2,  Q = (u_lo - u_hi)/2 (len 16)
//   per pair:     d1 = cyclic16(P_i,P_j), d2 = negacyclic16(Q_i,Q_j),
//                 c2 = negacyclic32(v_i,v_j)
//   reconstruct:  c1[n<16] = d1+d2, c1[16..31] = d1-d2
//                 out[n<32] = c1+c2, out[32..63] = c1-c2
// 1536 FMAs/pair vs 4096 direct; inner loops use packed fma.rn.f32x2.

#define NF 24
#define NPAIR 276
#define LEN 64
#define THREADS 288
#define SV 65   // stride for 64-entry rows (65 mod 32 == 1 -> distinct banks)
#define SP 33   // stride for 32-entry rows (33 mod 32 == 1)

__device__ __forceinline__ void ffma2(float2& d, float2 a, float2 b) {
    asm("fma.rn.f32x2 %0, %1, %2, %0;"
        : "+l"(*reinterpret_cast<unsigned long long*>(&d))
        : "l"(*reinterpret_cast<unsigned long long*>(&a)),
          "l"(*reinterpret_cast<unsigned long long*>(&b)));
}

// Length-N convolution (cyclic or negacyclic depending on buffer contents):
//   acc[q] = ( out[q], out[q+N/2] ),  out[n] = sum_k A[k+N] * B[n-k+N]
// B[t] for t in [0, 2N): extended/duplicated (with sign for negacyclic) operand.
// A[k+N] for k in [0, N): the "a" operand (upper half of the same buffer type).
template <int N>
__device__ __forceinline__ void conv_half(const float* __restrict__ A,
                                          const float* __restrict__ B,
                                          float2* __restrict__ acc)
{
    constexpr int H = N / 2;
    float2 w[H];
#pragma unroll
    for (int q = 0; q < H; ++q) {
        w[q]   = make_float2(B[q + N], B[q + N + H]);
        acc[q] = make_float2(0.f, 0.f);
    }
#pragma unroll
    for (int k = 0; k < N; ++k) {
        const float a = A[k + N];
        const float2 aa = make_float2(a, a);
#pragma unroll
        for (int q = 0; q < H; ++q)
            ffma2(acc[q], aa, w[q]);
        const float nw   = B[N - 1 - k];
        const float keep = w[H - 1].x;
#pragma unroll
        for (int q = H - 1; q > 0; --q) w[q] = w[q - 1];
        w[0] = make_float2(nw, keep);
    }
}

__global__ __launch_bounds__(THREADS, 2)
void holo_crt_kernel(const float* __restrict__ in, float* __restrict__ out)
{
    __shared__ float bufV[NF * SV];  // negacyclic-32 operand, scaled by 1/sqrt(2)
    __shared__ float bufP[NF * SP];  // cyclic-16 operand (duplicated), scaled by 1/2
    __shared__ float bufQ[NF * SP];  // negacyclic-16 operand, scaled by 1/2

    const int batch = blockIdx.x;
    const float* __restrict__ src = in + (size_t)batch * (NF * LEN);

    // ---- per-field folds (shared by all pairs) ----
    for (int idx = threadIdx.x; idx < NF * 16; idx += THREADS) {
        const int f = idx >> 4, m = idx & 15;
        const float* x = src + f * LEN;
        const float x0 = x[m], x1 = x[m + 16], x2 = x[m + 32], x3 = x[m + 48];
        const float s = 0.70710678118654752f;
        const float vlo = (x0 - x2) * s, vhi = (x1 - x3) * s;
        const float ulo = x0 + x2,       uhi = x1 + x3;
        const float P = (ulo + uhi) * 0.5f, Q = (ulo - uhi) * 0.5f;
        float* bV = bufV + f * SV;
        bV[m]      = -vlo;  bV[m + 16] = -vhi;   // t<32: -v[t]
        bV[m + 32] =  vlo;  bV[m + 48] =  vhi;   // t>=32: v[t-32]
        float* bP = bufP + f * SP;
        bP[m] = P;  bP[m + 16] = P;              // duplicated (cyclic)
        float* bQ = bufQ + f * SP;
        bQ[m] = -Q; bQ[m + 16] = Q;              // sign-flipped (negacyclic)
    }
    __syncthreads();

    const int t = threadIdx.x;
    if (t >= NPAIR) return;

    // decode (i, j) from pair index (row-major triu, k=1)
    int i = 0, rem = t;
    while (rem >= NF - 1 - i) { rem -= NF - 1 - i; ++i; }
    const int j = i + 1 + rem;

    float2 av[16], a1[8], a2[8];
    conv_half<32>(bufV + i * SV, bufV + j * SV, av);  // c2' = negacyclic32 / 2
    conv_half<16>(bufP + i * SP, bufP + j * SP, a1);  // d1' = cyclic16 / 4
    conv_half<16>(bufQ + i * SP, bufQ + j * SP, a2);  // d2' = negacyclic16 / 4

    // ---- reconstruct & store ----
    float4* __restrict__ dst = (float4*)(out + ((size_t)batch * NPAIR + t) * LEN);
#pragma unroll
    for (int g = 0; g < 8; ++g) {
        float lo[4], hi[4];
#pragma unroll
        for (int r = 0; r < 4; ++r) {
            const int n = 4 * g + r;      // n in [0,32)
            const int q = n & 7;
            float c1;
            if (n < 8)        c1 = a1[q].x + a2[q].x;
            else if (n < 16)  c1 = a1[q].y + a2[q].y;
            else if (n < 24)  c1 = a1[q].x - a2[q].x;
            else              c1 = a1[q].y - a2[q].y;
            const float c2 = (n < 16) ? av[n].x : av[n & 15].y;
            lo[r] = c1 + c2;              // out[n]
            hi[r] = c1 - c2;              // out[n+32]
        }
        dst[g]     = make_float4(lo[0], lo[1], lo[2], lo[3]);
        dst[g + 8] = make_float4(hi[0], hi[1], hi[2], hi[3]);
    }
}

extern "C" void kernel_launch(void* const* d_in, const int* in_sizes, int n_in,
                              void* d_out, int out_size)
{
    const float* in  = (const float*)d_in[0];
    float*       out = (float*)d_out;
    const int batches = in_sizes[0] / (NF * LEN);   // 2048 for the bench shape
    holo_crt_kernel<<<batches, THREADS>>>(in, out);
}